// round 1
// baseline (speedup 1.0000x reference)
#include <cuda_runtime.h>

#define S_LEN 2048
#define NB 2
#define DM 1024
#define NH 16
#define DKH 64
#define BH (NB * NH)

// Scratch (allocation-free rule: __device__ globals). 4 x 16MB = 64MB.
__device__ float g_Q[NB * NH * S_LEN * DKH];
__device__ float g_K[NB * NH * S_LEN * DKH];
__device__ float g_V[NB * NH * S_LEN * DKH];
__device__ float g_ctx[NB * S_LEN * DM];

// ---------------------------------------------------------------------------
// 128x128 tile, BK=8 fp32 GEMM: C = A[4096,1024] @ B[1024,1024] + bias
// MODE 0/1/2: write to g_Q/g_K/g_V in [B,H,S,dk] layout
// MODE 3:     A := g_ctx, write flat [4096,1024] to C
// ---------------------------------------------------------------------------
template <int MODE>
__global__ __launch_bounds__(256) void gemm_bias_kernel(
    const float* __restrict__ A, const float* __restrict__ B,
    const float* __restrict__ bias, float* __restrict__ C)
{
    __shared__ float As[8][128];
    __shared__ float Bs[8][128];
    const int K = DM, N = DM;
    const float* Ap = (MODE == 3) ? (const float*)g_ctx : A;

    int tid = threadIdx.x;
    int ty = tid >> 4, tx = tid & 15;
    int row0 = blockIdx.y * 128, col0 = blockIdx.x * 128;

    float acc[8][8];
#pragma unroll
    for (int i = 0; i < 8; i++)
#pragma unroll
        for (int j = 0; j < 8; j++) acc[i][j] = 0.f;

    int arow = tid >> 1, akc = (tid & 1) * 4;     // A tile: 128 rows x 8 k
    int bkr = tid >> 5, bnc = (tid & 31) * 4;     // B tile: 8 k x 128 cols
    const float* Aptr = Ap + (size_t)(row0 + arow) * K + akc;
    const float* Bptr = B + (size_t)bkr * N + col0 + bnc;

    for (int k0 = 0; k0 < K; k0 += 8) {
        float4 av = *(const float4*)(Aptr + k0);
        As[akc + 0][arow] = av.x; As[akc + 1][arow] = av.y;
        As[akc + 2][arow] = av.z; As[akc + 3][arow] = av.w;
        *(float4*)&Bs[bkr][bnc] = *(const float4*)(Bptr + (size_t)k0 * N);
        __syncthreads();
#pragma unroll
        for (int k = 0; k < 8; k++) {
            float4 a0 = *(float4*)&As[k][ty * 8];
            float4 a1 = *(float4*)&As[k][ty * 8 + 4];
            float4 b0 = *(float4*)&Bs[k][tx * 8];
            float4 b1 = *(float4*)&Bs[k][tx * 8 + 4];
            float ar[8] = {a0.x, a0.y, a0.z, a0.w, a1.x, a1.y, a1.z, a1.w};
            float br[8] = {b0.x, b0.y, b0.z, b0.w, b1.x, b1.y, b1.z, b1.w};
#pragma unroll
            for (int i = 0; i < 8; i++)
#pragma unroll
                for (int j = 0; j < 8; j++) acc[i][j] += ar[i] * br[j];
        }
        __syncthreads();
    }

#pragma unroll
    for (int i = 0; i < 8; i++) {
        int row = row0 + ty * 8 + i;
#pragma unroll
        for (int j = 0; j < 8; j++) {
            int col = col0 + tx * 8 + j;
            float v = acc[i][j] + bias[col];
            if (MODE == 3) {
                C[(size_t)row * N + col] = v;
            } else {
                int b = row >> 11, s = row & 2047, h = col >> 6, d = col & 63;
                float* dst = (MODE == 0) ? g_Q : (MODE == 1) ? g_K : g_V;
                dst[(((size_t)(b << 4) + h) * S_LEN + s) * DKH + d] = v;
            }
        }
    }
}

// ---------------------------------------------------------------------------
// scores[bh] = Q_h @ K_h^T * 0.125   (per head: [2048,64] x [64,2048])
// writes raw scores into the weights region of d_out (softmaxed in-place next)
// ---------------------------------------------------------------------------
__global__ __launch_bounds__(256) void scores_kernel(float* __restrict__ W)
{
    __shared__ float As[8][128];
    __shared__ float Bs[8][128];
    int bh = blockIdx.z;
    const float* Qh = g_Q + (size_t)bh * S_LEN * DKH;
    const float* Kh = g_K + (size_t)bh * S_LEN * DKH;
    float* Wh = W + (size_t)bh * S_LEN * S_LEN;

    int tid = threadIdx.x;
    int ty = tid >> 4, tx = tid & 15;
    int row0 = blockIdx.y * 128, col0 = blockIdx.x * 128;

    float acc[8][8];
#pragma unroll
    for (int i = 0; i < 8; i++)
#pragma unroll
        for (int j = 0; j < 8; j++) acc[i][j] = 0.f;

    int lrow = tid >> 1, lkc = (tid & 1) * 4;

    for (int k0 = 0; k0 < DKH; k0 += 8) {
        float4 av = *(const float4*)(Qh + (size_t)(row0 + lrow) * DKH + k0 + lkc);
        As[lkc + 0][lrow] = av.x; As[lkc + 1][lrow] = av.y;
        As[lkc + 2][lrow] = av.z; As[lkc + 3][lrow] = av.w;
        float4 bv = *(const float4*)(Kh + (size_t)(col0 + lrow) * DKH + k0 + lkc);
        Bs[lkc + 0][lrow] = bv.x; Bs[lkc + 1][lrow] = bv.y;
        Bs[lkc + 2][lrow] = bv.z; Bs[lkc + 3][lrow] = bv.w;
        __syncthreads();
#pragma unroll
        for (int k = 0; k < 8; k++) {
            float4 a0 = *(float4*)&As[k][ty * 8];
            float4 a1 = *(float4*)&As[k][ty * 8 + 4];
            float4 b0 = *(float4*)&Bs[k][tx * 8];
            float4 b1 = *(float4*)&Bs[k][tx * 8 + 4];
            float ar[8] = {a0.x, a0.y, a0.z, a0.w, a1.x, a1.y, a1.z, a1.w};
            float br[8] = {b0.x, b0.y, b0.z, b0.w, b1.x, b1.y, b1.z, b1.w};
#pragma unroll
            for (int i = 0; i < 8; i++)
#pragma unroll
                for (int j = 0; j < 8; j++) acc[i][j] += ar[i] * br[j];
        }
        __syncthreads();
    }

#pragma unroll
    for (int i = 0; i < 8; i++) {
        int row = row0 + ty * 8 + i;
#pragma unroll
        for (int j = 0; j < 8; j++) {
            int col = col0 + tx * 8 + j;
            Wh[(size_t)row * S_LEN + col] = acc[i][j] * 0.125f;  // 1/sqrt(64)
        }
    }
}

// ---------------------------------------------------------------------------
// In-place row softmax over 2048 cols. One block (256 thr) per row.
// ---------------------------------------------------------------------------
__global__ __launch_bounds__(256) void softmax_kernel(float* __restrict__ W)
{
    __shared__ float red[256];
    float* p = W + (size_t)blockIdx.x * S_LEN;
    int tid = threadIdx.x;
    float v[8];
    float m = -1e30f;
#pragma unroll
    for (int i = 0; i < 8; i++) {
        v[i] = p[tid + i * 256];
        m = fmaxf(m, v[i]);
    }
    red[tid] = m;
    __syncthreads();
    for (int s = 128; s > 0; s >>= 1) {
        if (tid < s) red[tid] = fmaxf(red[tid], red[tid + s]);
        __syncthreads();
    }
    m = red[0];
    __syncthreads();
    float sum = 0.f;
#pragma unroll
    for (int i = 0; i < 8; i++) {
        v[i] = __expf(v[i] - m);
        sum += v[i];
    }
    red[tid] = sum;
    __syncthreads();
    for (int s = 128; s > 0; s >>= 1) {
        if (tid < s) red[tid] += red[tid + s];
        __syncthreads();
    }
    float inv = 1.0f / red[0];
#pragma unroll
    for (int i = 0; i < 8; i++) p[tid + i * 256] = v[i] * inv;
}

// ---------------------------------------------------------------------------
// context[bh] = W_h[2048,2048] @ V_h[2048,64] -> g_ctx in [B,S,D] layout
// BM=128, BN=64, BK=16; 256 threads, 4x8 microtile
// ---------------------------------------------------------------------------
__global__ __launch_bounds__(256) void context_kernel(const float* __restrict__ W)
{
    __shared__ float As[16][128];
    __shared__ float Bs[16][64];
    int bh = blockIdx.z;
    const float* Wh = W + (size_t)bh * S_LEN * S_LEN;
    const float* Vh = g_V + (size_t)bh * S_LEN * DKH;
    int b = bh >> 4, h = bh & 15;

    int tid = threadIdx.x;
    int ty = tid >> 3, tx = tid & 7;   // ty 0..31, tx 0..7
    int row0 = blockIdx.y * 128;

    float acc[4][8];
#pragma unroll
    for (int i = 0; i < 4; i++)
#pragma unroll
        for (int j = 0; j < 8; j++) acc[i][j] = 0.f;

    int arow = tid >> 2, akc = (tid & 3) * 4;     // arow 0..63
    int bkr = tid >> 4, bnc = (tid & 15) * 4;     // bkr 0..15

    for (int k0 = 0; k0 < S_LEN; k0 += 16) {
#pragma unroll
        for (int rr = 0; rr < 2; rr++) {
            int r = arow + rr * 64;
            float4 av = *(const float4*)(Wh + (size_t)(row0 + r) * S_LEN + k0 + akc);
            As[akc + 0][r] = av.x; As[akc + 1][r] = av.y;
            As[akc + 2][r] = av.z; As[akc + 3][r] = av.w;
        }
        *(float4*)&Bs[bkr][bnc] = *(const float4*)(Vh + (size_t)(k0 + bkr) * DKH + bnc);
        __syncthreads();
#pragma unroll
        for (int k = 0; k < 16; k++) {
            float4 a0 = *(float4*)&As[k][ty * 4];
            float4 b0 = *(float4*)&Bs[k][tx * 8];
            float4 b1 = *(float4*)&Bs[k][tx * 8 + 4];
            float ar[4] = {a0.x, a0.y, a0.z, a0.w};
            float br[8] = {b0.x, b0.y, b0.z, b0.w, b1.x, b1.y, b1.z, b1.w};
#pragma unroll
            for (int i = 0; i < 4; i++)
#pragma unroll
                for (int j = 0; j < 8; j++) acc[i][j] += ar[i] * br[j];
        }
        __syncthreads();
    }

#pragma unroll
    for (int i = 0; i < 4; i++) {
        int row = row0 + ty * 4 + i;
#pragma unroll
        for (int j = 0; j < 8; j++) {
            int col = tx * 8 + j;
            g_ctx[((size_t)b * S_LEN + row) * DM + h * DKH + col] = acc[i][j];
        }
    }
}

// ---------------------------------------------------------------------------
extern "C" void kernel_launch(void* const* d_in, const int* in_sizes, int n_in,
                              void* d_out, int out_size)
{
    const float* query = (const float*)d_in[0];
    const float* key_  = (const float*)d_in[1];
    const float* value = (const float*)d_in[2];
    const float* Wq = (const float*)d_in[3];
    const float* bq = (const float*)d_in[4];
    const float* Wk = (const float*)d_in[5];
    const float* bk = (const float*)d_in[6];
    const float* Wv = (const float*)d_in[7];
    const float* bv = (const float*)d_in[8];
    const float* Wo = (const float*)d_in[9];
    const float* bo = (const float*)d_in[10];

    float* out = (float*)d_out;                                  // [2,2048,1024]
    float* weights = out + (size_t)NB * S_LEN * DM;              // [2,16,2048,2048]

    dim3 blk(256);
    dim3 gProj(DM / 128, (NB * S_LEN) / 128);                    // (8, 32)
    gemm_bias_kernel<0><<<gProj, blk>>>(query, Wq, bq, nullptr);
    gemm_bias_kernel<1><<<gProj, blk>>>(key_,  Wk, bk, nullptr);
    gemm_bias_kernel<2><<<gProj, blk>>>(value, Wv, bv, nullptr);

    dim3 gScore(S_LEN / 128, S_LEN / 128, BH);                   // (16, 16, 32)
    scores_kernel<<<gScore, blk>>>(weights);

    softmax_kernel<<<BH * S_LEN, blk>>>(weights);                // 65536 rows

    dim3 gCtx(1, S_LEN / 128, BH);                               // (1, 16, 32)
    context_kernel<<<gCtx, blk>>>(weights);

    gemm_bias_kernel<3><<<gProj, blk>>>(nullptr, Wo, bo, out);
}